// round 5
// baseline (speedup 1.0000x reference)
#include <cuda_runtime.h>
#include <math_constants.h>

static constexpr int K  = 1024;
static constexpr int D  = 64;
static constexpr int C  = 32;
static constexpr int NT = 128;       // threads per CTA
static constexpr int NW = NT / 32;   // 4 warps
static constexpr int NG = NT / 8;    // 16 key-groups in pass 2

__global__ __launch_bounds__(NT, 11) void nw_attn_kernel(
    const float* __restrict__ x,
    const float* __restrict__ keys,
    const float* __restrict__ values,
    const float* __restrict__ gamma,
    float* __restrict__ out)
{
    __shared__ float s_scores[K];          // 4 KB scores
    __shared__ float s_red[NW];            // per-warp max
    __shared__ float s_z[NW];              // per-warp Z partials
    __shared__ float s_acc[NG][C + 1];     // padded rows: conflict-free column reads

    const int b    = blockIdx.x;
    const int tid  = threadIdx.x;
    const int lane = tid & 31;
    const int warp = tid >> 5;

    const float g = gamma[0];

    // ---- Pass 1: 4 lanes per key, 8 keys per warp-iter ----
    const int l4 = lane & 3;               // dim-group of 16 floats
    const int kw = lane >> 2;              // key within 8-key tile

    const float* xb = x + (size_t)b * D + l4 * 16;
    const float4 xq0 = *reinterpret_cast<const float4*>(xb + 0);
    const float4 xq1 = *reinterpret_cast<const float4*>(xb + 4);
    const float4 xq2 = *reinterpret_cast<const float4*>(xb + 8);
    const float4 xq3 = *reinterpret_cast<const float4*>(xb + 12);

    const float* kb = keys + (size_t)b * K * D;

    float lmax = -CUDART_INF_F;
    #pragma unroll 2
    for (int k0 = warp * 8; k0 < K; k0 += NW * 8) {   // 32 iters/warp
        const int key = k0 + kw;
        const float4* p = reinterpret_cast<const float4*>(
                              kb + (size_t)key * D + l4 * 16);
        // 4 independent 16B loads per lane (high MLP)
        const float4 a0 = __ldcs(p + 0);
        const float4 a1 = __ldcs(p + 1);
        const float4 a2 = __ldcs(p + 2);
        const float4 a3 = __ldcs(p + 3);

        float d, ss;
        d = xq0.x - a0.x; ss  = d * d;
        d = xq0.y - a0.y; ss = fmaf(d, d, ss);
        d = xq0.z - a0.z; ss = fmaf(d, d, ss);
        d = xq0.w - a0.w; ss = fmaf(d, d, ss);
        d = xq1.x - a1.x; ss = fmaf(d, d, ss);
        d = xq1.y - a1.y; ss = fmaf(d, d, ss);
        d = xq1.z - a1.z; ss = fmaf(d, d, ss);
        d = xq1.w - a1.w; ss = fmaf(d, d, ss);
        d = xq2.x - a2.x; ss = fmaf(d, d, ss);
        d = xq2.y - a2.y; ss = fmaf(d, d, ss);
        d = xq2.z - a2.z; ss = fmaf(d, d, ss);
        d = xq2.w - a2.w; ss = fmaf(d, d, ss);
        d = xq3.x - a3.x; ss = fmaf(d, d, ss);
        d = xq3.y - a3.y; ss = fmaf(d, d, ss);
        d = xq3.z - a3.z; ss = fmaf(d, d, ss);
        d = xq3.w - a3.w; ss = fmaf(d, d, ss);

        // reduce across the 4 lanes of this key
        ss += __shfl_xor_sync(0xffffffffu, ss, 1);
        ss += __shfl_xor_sync(0xffffffffu, ss, 2);

        const float s = -g * ss;
        if (l4 == 0) s_scores[key] = s;
        lmax = fmaxf(lmax, s);
    }

    // ---- block max ----
    #pragma unroll
    for (int o = 16; o; o >>= 1)
        lmax = fmaxf(lmax, __shfl_xor_sync(0xffffffffu, lmax, o));
    if (lane == 0) s_red[warp] = lmax;
    __syncthreads();                       // scores + maxes visible
    float M = s_red[0];
    #pragma unroll
    for (int w = 1; w < NW; w++) M = fmaxf(M, s_red[w]);

    // ---- Pass 2: exp on the fly + weighted sum over values ----
    const float* vb = values + (size_t)b * K * C;
    const int kgrp = tid >> 3;             // 0..15
    const int cq   = (tid & 7) * 4;        // channel offset
    const bool zlane = (tid & 7) == 0;

    float4 acc = make_float4(0.f, 0.f, 0.f, 0.f);
    float wsum = 0.f;
    #pragma unroll 8
    for (int i = 0; i < K / NG; i++) {     // 64 iters
        const int k = kgrp + NG * i;
        const float w = __expf(s_scores[k] - M);
        const float4 v = __ldcs(reinterpret_cast<const float4*>(
                                    vb + (size_t)k * C + cq));
        acc.x = fmaf(w, v.x, acc.x);
        acc.y = fmaf(w, v.y, acc.y);
        acc.z = fmaf(w, v.z, acc.z);
        acc.w = fmaf(w, v.w, acc.w);
        if (zlane) wsum += w;
    }

    // Z: warp reduce (only zlane contributed), then per-warp partials
    #pragma unroll
    for (int o = 16; o; o >>= 1)
        wsum += __shfl_xor_sync(0xffffffffu, wsum, o);
    if (lane == 0) s_z[warp] = wsum;

    // scalar stores: 33-float row stride is not 16B-aligned, no STS.128
    s_acc[kgrp][cq + 0] = acc.x;
    s_acc[kgrp][cq + 1] = acc.y;
    s_acc[kgrp][cq + 2] = acc.z;
    s_acc[kgrp][cq + 3] = acc.w;
    __syncthreads();

    if (tid < C) {
        float Z = 0.f;
        #pragma unroll
        for (int w = 0; w < NW; w++) Z += s_z[w];
        float r = 0.f;
        #pragma unroll
        for (int gk = 0; gk < NG; gk++) r += s_acc[gk][tid];
        out[(size_t)b * C + tid] = r * (1.0f / Z);
    }
}

extern "C" void kernel_launch(void* const* d_in, const int* in_sizes, int n_in,
                              void* d_out, int out_size)
{
    const float* x      = (const float*)d_in[0];
    const float* keys   = (const float*)d_in[1];
    const float* values = (const float*)d_in[2];
    const float* gamma  = (const float*)d_in[3];
    float* out = (float*)d_out;

    const int B = in_sizes[0] / D;     // 2048
    nw_attn_kernel<<<B, NT>>>(x, keys, values, gamma, out);
}

// round 6
// speedup vs baseline: 1.1216x; 1.1216x over previous
#include <cuda_runtime.h>
#include <math_constants.h>

static constexpr int K  = 1024;
static constexpr int D  = 64;
static constexpr int C  = 32;
static constexpr int NT = 256;
static constexpr int NW = NT / 32;

struct XQ { float4 q0, q1, q2, q3; };

__device__ __forceinline__ XQ load_x(const float* x, int b, int l4)
{
    const float* xb = x + (size_t)b * D + l4 * 16;
    XQ r;
    r.q0 = *reinterpret_cast<const float4*>(xb + 0);
    r.q1 = *reinterpret_cast<const float4*>(xb + 4);
    r.q2 = *reinterpret_cast<const float4*>(xb + 8);
    r.q3 = *reinterpret_cast<const float4*>(xb + 12);
    return r;
}

// stream 256KB of keys, write scores + per-warp max
__device__ __forceinline__ void pass1(
    const float* kb, const XQ& xq, float g,
    int warp, int lane, float* s_scores, float* s_red)
{
    const int l4 = lane & 3;
    const int kw = lane >> 2;
    float lmax = -CUDART_INF_F;
    #pragma unroll 2
    for (int k0 = warp * 8; k0 < K; k0 += NW * 8) {
        const int key = k0 + kw;
        const float4* p = reinterpret_cast<const float4*>(
                              kb + (size_t)key * D + l4 * 16);
        const float4 a0 = __ldcs(p + 0);
        const float4 a1 = __ldcs(p + 1);
        const float4 a2 = __ldcs(p + 2);
        const float4 a3 = __ldcs(p + 3);

        float d, ss;
        d = xq.q0.x - a0.x; ss  = d * d;
        d = xq.q0.y - a0.y; ss = fmaf(d, d, ss);
        d = xq.q0.z - a0.z; ss = fmaf(d, d, ss);
        d = xq.q0.w - a0.w; ss = fmaf(d, d, ss);
        d = xq.q1.x - a1.x; ss = fmaf(d, d, ss);
        d = xq.q1.y - a1.y; ss = fmaf(d, d, ss);
        d = xq.q1.z - a1.z; ss = fmaf(d, d, ss);
        d = xq.q1.w - a1.w; ss = fmaf(d, d, ss);
        d = xq.q2.x - a2.x; ss = fmaf(d, d, ss);
        d = xq.q2.y - a2.y; ss = fmaf(d, d, ss);
        d = xq.q2.z - a2.z; ss = fmaf(d, d, ss);
        d = xq.q2.w - a2.w; ss = fmaf(d, d, ss);
        d = xq.q3.x - a3.x; ss = fmaf(d, d, ss);
        d = xq.q3.y - a3.y; ss = fmaf(d, d, ss);
        d = xq.q3.z - a3.z; ss = fmaf(d, d, ss);
        d = xq.q3.w - a3.w; ss = fmaf(d, d, ss);

        ss += __shfl_xor_sync(0xffffffffu, ss, 1);
        ss += __shfl_xor_sync(0xffffffffu, ss, 2);

        const float s = -g * ss;
        if (l4 == 0) s_scores[key] = s;
        lmax = fmaxf(lmax, s);
    }
    #pragma unroll
    for (int o = 16; o; o >>= 1)
        lmax = fmaxf(lmax, __shfl_xor_sync(0xffffffffu, lmax, o));
    if (lane == 0) s_red[warp] = lmax;
}

__device__ __forceinline__ float block_max(const float* s_red)
{
    float M = s_red[0];
    #pragma unroll
    for (int w = 1; w < NW; w++) M = fmaxf(M, s_red[w]);
    return M;
}

// stream 128KB of values, exp on the fly, partials to smem
__device__ __forceinline__ void pass2(
    const float* vb, const float* s_scores, float M,
    int tid, int lane, int warp,
    float* s_z, float (*s_acc)[C + 1])
{
    const int kgrp = tid >> 3;             // 0..31
    const int cq   = (tid & 7) * 4;
    const bool zlane = (tid & 7) == 0;

    float4 acc = make_float4(0.f, 0.f, 0.f, 0.f);
    float wsum = 0.f;
    #pragma unroll 8
    for (int i = 0; i < K / 32; i++) {
        const int k = kgrp + 32 * i;
        const float w = __expf(s_scores[k] - M);
        const float4 v = __ldcs(reinterpret_cast<const float4*>(
                                    vb + (size_t)k * C + cq));
        acc.x = fmaf(w, v.x, acc.x);
        acc.y = fmaf(w, v.y, acc.y);
        acc.z = fmaf(w, v.z, acc.z);
        acc.w = fmaf(w, v.w, acc.w);
        if (zlane) wsum += w;
    }
    #pragma unroll
    for (int o = 16; o; o >>= 1)
        wsum += __shfl_xor_sync(0xffffffffu, wsum, o);
    if (lane == 0) s_z[warp] = wsum;

    // scalar stores: 33-float row stride not 16B aligned
    s_acc[kgrp][cq + 0] = acc.x;
    s_acc[kgrp][cq + 1] = acc.y;
    s_acc[kgrp][cq + 2] = acc.z;
    s_acc[kgrp][cq + 3] = acc.w;
}

__device__ __forceinline__ void finalize(
    const float* s_z, const float (*s_acc)[C + 1], float* outp, int tid)
{
    if (tid < C) {
        float Z = 0.f;
        #pragma unroll
        for (int w = 0; w < NW; w++) Z += s_z[w];
        float r = 0.f;
        #pragma unroll
        for (int gk = 0; gk < C; gk++) r += s_acc[gk][tid];
        outp[tid] = r * (1.0f / Z);
    }
}

__global__ __launch_bounds__(NT, 5) void nw_attn_pipe(
    const float* __restrict__ x,
    const float* __restrict__ keys,
    const float* __restrict__ values,
    const float* __restrict__ gamma,
    float* __restrict__ out)
{
    __shared__ float s_scores[2][K];            // 8 KB
    __shared__ float s_red[2][NW];
    __shared__ float s_z[2][NW];
    __shared__ float s_acc[2][C][C + 1];        // 8.25 KB, padded

    const int b0   = blockIdx.x * 2;
    const int b1   = b0 + 1;
    const int tid  = threadIdx.x;
    const int lane = tid & 31;
    const int warp = tid >> 5;
    const int l4   = lane & 3;

    const float g = gamma[0];

    const XQ x0 = load_x(x, b0, l4);
    pass1(keys + (size_t)b0 * K * D, x0, g, warp, lane, s_scores[0], s_red[0]);
    __syncthreads();                                    // bar1

    const float M0 = block_max(s_red[0]);
    pass2(values + (size_t)b0 * K * C, s_scores[0], M0,
          tid, lane, warp, s_z[0], s_acc[0]);
    // NO barrier: roll straight into next row's key stream
    const XQ x1 = load_x(x, b1, l4);
    pass1(keys + (size_t)b1 * K * D, x1, g, warp, lane, s_scores[1], s_red[1]);
    __syncthreads();                                    // bar2

    finalize(s_z[0], s_acc[0], out + (size_t)b0 * C, tid);
    const float M1 = block_max(s_red[1]);
    pass2(values + (size_t)b1 * K * C, s_scores[1], M1,
          tid, lane, warp, s_z[1], s_acc[1]);
    __syncthreads();                                    // bar3

    finalize(s_z[1], s_acc[1], out + (size_t)b1 * C, tid);
}

extern "C" void kernel_launch(void* const* d_in, const int* in_sizes, int n_in,
                              void* d_out, int out_size)
{
    const float* x      = (const float*)d_in[0];
    const float* keys   = (const float*)d_in[1];
    const float* values = (const float*)d_in[2];
    const float* gamma  = (const float*)d_in[3];
    float* out = (float*)d_out;

    const int B = in_sizes[0] / D;     // 2048
    nw_attn_pipe<<<B / 2, NT>>>(x, keys, values, gamma, out);
}

// round 7
// speedup vs baseline: 1.1569x; 1.0315x over previous
#include <cuda_runtime.h>
#include <math_constants.h>

static constexpr int K  = 1024;
static constexpr int D  = 64;
static constexpr int C  = 32;
static constexpr int NT = 256;
static constexpr int NW = NT / 32;
static constexpr int BMAX = 2048;

// scratch (allocation-free): scores + per-half-row maxes
__device__ float g_scores[(size_t)BMAX * K];      // 8 MB, L2-resident
__device__ float g_max[BMAX * 2];

// ---------------- Kernel 1: key streamer -> scores + half-row max --------
__global__ __launch_bounds__(NT) void nw_pass1(
    const float* __restrict__ x,
    const float* __restrict__ keys,
    const float* __restrict__ gamma)
{
    __shared__ float s_red[NW];

    const int cta  = blockIdx.x;
    const int b    = cta >> 1;
    const int h    = cta & 1;            // which half of the key range
    const int tid  = threadIdx.x;
    const int lane = tid & 31;
    const int warp = tid >> 5;

    const int l4 = lane & 3;             // 16-float dim chunk
    const int kw = lane >> 2;            // key slot 0..7

    const float g = gamma[0];

    const float* xb = x + (size_t)b * D + l4 * 16;
    const float4 xq0 = *reinterpret_cast<const float4*>(xb + 0);
    const float4 xq1 = *reinterpret_cast<const float4*>(xb + 4);
    const float4 xq2 = *reinterpret_cast<const float4*>(xb + 8);
    const float4 xq3 = *reinterpret_cast<const float4*>(xb + 12);

    const float* kb = keys + (size_t)b * K * D;
    float* sc = g_scores + (size_t)b * K;

    const int kbeg = h * (K / 2);
    const int kend = kbeg + (K / 2);

    float lmax = -CUDART_INF_F;
    #pragma unroll 2
    for (int k0 = kbeg + warp * 8; k0 < kend; k0 += NW * 8) {  // 8 iters/warp
        const int key = k0 + kw;
        const float4* p = reinterpret_cast<const float4*>(
                              kb + (size_t)key * D + l4 * 16);
        const float4 a0 = __ldcs(p + 0);
        const float4 a1 = __ldcs(p + 1);
        const float4 a2 = __ldcs(p + 2);
        const float4 a3 = __ldcs(p + 3);

        float d, ss;
        d = xq0.x - a0.x; ss  = d * d;
        d = xq0.y - a0.y; ss = fmaf(d, d, ss);
        d = xq0.z - a0.z; ss = fmaf(d, d, ss);
        d = xq0.w - a0.w; ss = fmaf(d, d, ss);
        d = xq1.x - a1.x; ss = fmaf(d, d, ss);
        d = xq1.y - a1.y; ss = fmaf(d, d, ss);
        d = xq1.z - a1.z; ss = fmaf(d, d, ss);
        d = xq1.w - a1.w; ss = fmaf(d, d, ss);
        d = xq2.x - a2.x; ss = fmaf(d, d, ss);
        d = xq2.y - a2.y; ss = fmaf(d, d, ss);
        d = xq2.z - a2.z; ss = fmaf(d, d, ss);
        d = xq2.w - a2.w; ss = fmaf(d, d, ss);
        d = xq3.x - a3.x; ss = fmaf(d, d, ss);
        d = xq3.y - a3.y; ss = fmaf(d, d, ss);
        d = xq3.z - a3.z; ss = fmaf(d, d, ss);
        d = xq3.w - a3.w; ss = fmaf(d, d, ss);

        ss += __shfl_xor_sync(0xffffffffu, ss, 1);
        ss += __shfl_xor_sync(0xffffffffu, ss, 2);

        const float s = -g * ss;
        if (l4 == 0) sc[key] = s;        // default caching -> L2 resident
        lmax = fmaxf(lmax, s);
    }

    #pragma unroll
    for (int o = 16; o; o >>= 1)
        lmax = fmaxf(lmax, __shfl_xor_sync(0xffffffffu, lmax, o));
    if (lane == 0) s_red[warp] = lmax;
    __syncthreads();
    if (tid == 0) {
        float M = s_red[0];
        #pragma unroll
        for (int w = 1; w < NW; w++) M = fmaxf(M, s_red[w]);
        g_max[cta] = M;
    }
}

// ---------------- Kernel 2: value streamer -> output ---------------------
__global__ __launch_bounds__(NT) void nw_pass2(
    const float* __restrict__ values,
    float* __restrict__ out)
{
    __shared__ float s_z[NW];
    __shared__ float s_acc[C][C + 1];    // padded: conflict-free column reads

    const int b    = blockIdx.x;
    const int tid  = threadIdx.x;
    const int lane = tid & 31;
    const int warp = tid >> 5;

    const float M = fmaxf(g_max[2 * b], g_max[2 * b + 1]);

    const float* vb = values + (size_t)b * K * C;
    const float* sc = g_scores + (size_t)b * K;

    const int kgrp = tid >> 3;           // 0..31
    const int cq   = (tid & 7) * 4;
    const bool zlane = (tid & 7) == 0;

    float4 acc = make_float4(0.f, 0.f, 0.f, 0.f);
    float wsum = 0.f;
    #pragma unroll 8
    for (int i = 0; i < K / 32; i++) {
        const int k = kgrp + 32 * i;
        const float w = __expf(sc[k] - M);   // L2 hit, lane-broadcast
        const float4 v = __ldcs(reinterpret_cast<const float4*>(
                                    vb + (size_t)k * C + cq));
        acc.x = fmaf(w, v.x, acc.x);
        acc.y = fmaf(w, v.y, acc.y);
        acc.z = fmaf(w, v.z, acc.z);
        acc.w = fmaf(w, v.w, acc.w);
        if (zlane) wsum += w;
    }

    #pragma unroll
    for (int o = 16; o; o >>= 1)
        wsum += __shfl_xor_sync(0xffffffffu, wsum, o);
    if (lane == 0) s_z[warp] = wsum;

    // scalar stores: 33-float row stride not 16B-aligned
    s_acc[kgrp][cq + 0] = acc.x;
    s_acc[kgrp][cq + 1] = acc.y;
    s_acc[kgrp][cq + 2] = acc.z;
    s_acc[kgrp][cq + 3] = acc.w;
    __syncthreads();

    if (tid < C) {
        float Z = 0.f;
        #pragma unroll
        for (int w = 0; w < NW; w++) Z += s_z[w];
        float r = 0.f;
        #pragma unroll
        for (int gk = 0; gk < C; gk++) r += s_acc[gk][tid];
        out[(size_t)b * C + tid] = r * (1.0f / Z);
    }
}

extern "C" void kernel_launch(void* const* d_in, const int* in_sizes, int n_in,
                              void* d_out, int out_size)
{
    const float* x      = (const float*)d_in[0];
    const float* keys   = (const float*)d_in[1];
    const float* values = (const float*)d_in[2];
    const float* gamma  = (const float*)d_in[3];
    float* out = (float*)d_out;

    const int B = in_sizes[0] / D;       // 2048
    nw_pass1<<<B * 2, NT>>>(x, keys, gamma);
    nw_pass2<<<B, NT>>>(values, out);
}

// round 9
// speedup vs baseline: 1.2258x; 1.0596x over previous
#include <cuda_runtime.h>
#include <math_constants.h>

static constexpr int K  = 1024;
static constexpr int D  = 64;
static constexpr int C  = 32;
static constexpr int NT = 256;       // threads per CTA
static constexpr int NW = NT / 32;   // warps per CTA

__global__ __launch_bounds__(NT, 6) void nw_attn_kernel(
    const float* __restrict__ x,
    const float* __restrict__ keys,
    const float* __restrict__ values,
    const float* __restrict__ gamma,
    float* __restrict__ out)
{
    __shared__ float s_scores[K];          // 4 KB scores
    __shared__ float s_red[NW];            // per-warp max
    __shared__ float s_z[NW];              // per-warp Z partials
    __shared__ float s_acc[C][C + 1];      // padded rows: conflict-free columns

    const int b    = blockIdx.x;
    const int tid  = threadIdx.x;
    const int lane = tid & 31;
    const int warp = tid >> 5;

    const float g = gamma[0];

    // ---- Pass 1: coalesced instructions ----
    // instr i covers bytes [i*512, i*512+512) of the warp's 2KB (8-key) tile.
    // lane l -> key (2i + (l>>4)), dims [(l&15)*4, +4)
    const int l16 = lane & 15;
    const int h   = lane >> 4;

    const float4 xq = *reinterpret_cast<const float4*>(
                          x + (size_t)b * D + 4 * l16);

    const float* kb = keys + (size_t)b * K * D;

    float lmax = -CUDART_INF_F;
    #pragma unroll 2
    for (int k0 = warp * 8; k0 < K; k0 += NW * 8) {   // 16 iters/warp
        // 4 independent dense 512B loads
        const float4* p = reinterpret_cast<const float4*>(
                              kb + (size_t)(k0 + h) * D + 4 * l16);
        const float4 a0 = __ldcs(p + 0 * (2 * D / 4));   // key k0+h+0
        const float4 a1 = __ldcs(p + 1 * (2 * D / 4));   // key k0+h+2
        const float4 a2 = __ldcs(p + 2 * (2 * D / 4));   // key k0+h+4
        const float4 a3 = __ldcs(p + 3 * (2 * D / 4));   // key k0+h+6

        float d;
        float s0, s1, s2, s3;
        d = xq.x - a0.x; s0  = d * d;
        d = xq.y - a0.y; s0 = fmaf(d, d, s0);
        d = xq.z - a0.z; s0 = fmaf(d, d, s0);
        d = xq.w - a0.w; s0 = fmaf(d, d, s0);
        d = xq.x - a1.x; s1  = d * d;
        d = xq.y - a1.y; s1 = fmaf(d, d, s1);
        d = xq.z - a1.z; s1 = fmaf(d, d, s1);
        d = xq.w - a1.w; s1 = fmaf(d, d, s1);
        d = xq.x - a2.x; s2  = d * d;
        d = xq.y - a2.y; s2 = fmaf(d, d, s2);
        d = xq.z - a2.z; s2 = fmaf(d, d, s2);
        d = xq.w - a2.w; s2 = fmaf(d, d, s2);
        d = xq.x - a3.x; s3  = d * d;
        d = xq.y - a3.y; s3 = fmaf(d, d, s3);
        d = xq.z - a3.z; s3 = fmaf(d, d, s3);
        d = xq.w - a3.w; s3 = fmaf(d, d, s3);

        // reduce each over the 16 lanes sharing h (4 independent chains)
        #pragma unroll
        for (int o = 1; o <= 8; o <<= 1) {
            s0 += __shfl_xor_sync(0xffffffffu, s0, o);
            s1 += __shfl_xor_sync(0xffffffffu, s1, o);
            s2 += __shfl_xor_sync(0xffffffffu, s2, o);
            s3 += __shfl_xor_sync(0xffffffffu, s3, o);
        }
        s0 *= -g; s1 *= -g; s2 *= -g; s3 *= -g;

        // one lane per (i, h) stores its key's score
        if (l16 == 0) s_scores[k0 + h + 0] = s0;
        if (l16 == 1) s_scores[k0 + h + 2] = s1;
        if (l16 == 2) s_scores[k0 + h + 4] = s2;
        if (l16 == 3) s_scores[k0 + h + 6] = s3;

        lmax = fmaxf(lmax, fmaxf(fmaxf(s0, s1), fmaxf(s2, s3)));
    }

    // ---- block max ----
    #pragma unroll
    for (int o = 16; o; o >>= 1)
        lmax = fmaxf(lmax, __shfl_xor_sync(0xffffffffu, lmax, o));
    if (lane == 0) s_red[warp] = lmax;
    __syncthreads();                       // scores + maxes visible
    float M = s_red[0];
    #pragma unroll
    for (int w = 1; w < NW; w++) M = fmaxf(M, s_red[w]);

    // ---- Pass 2: exp on the fly + weighted sum over values ----
    const float* vb = values + (size_t)b * K * C;
    const int kgrp = tid >> 3;             // 0..31
    const int cq   = (tid & 7) * 4;        // channel offset
    const bool zlane = (tid & 7) == 0;

    float4 acc = make_float4(0.f, 0.f, 0.f, 0.f);
    float wsum = 0.f;
    #pragma unroll 8
    for (int i = 0; i < K / 32; i++) {
        const int k = kgrp + 32 * i;
        const float w = __expf(s_scores[k] - M);
        const float4 v = __ldcs(reinterpret_cast<const float4*>(
                                    vb + (size_t)k * C + cq));
        acc.x = fmaf(w, v.x, acc.x);
        acc.y = fmaf(w, v.y, acc.y);
        acc.z = fmaf(w, v.z, acc.z);
        acc.w = fmaf(w, v.w, acc.w);
        if (zlane) wsum += w;
    }

    // Z: warp reduce (only zlane contributed), then per-warp partials
    #pragma unroll
    for (int o = 16; o; o >>= 1)
        wsum += __shfl_xor_sync(0xffffffffu, wsum, o);
    if (lane == 0) s_z[warp] = wsum;

    // scalar stores: 33-float row stride is not 16B-aligned, no STS.128
    s_acc[kgrp][cq + 0] = acc.x;
    s_acc[kgrp][cq + 1] = acc.y;
    s_acc[kgrp][cq + 2] = acc.z;
    s_acc[kgrp][cq + 3] = acc.w;
    __syncthreads();

    if (tid < C) {
        float Z = 0.f;
        #pragma unroll
        for (int w = 0; w < NW; w++) Z += s_z[w];
        float r = 0.f;
        #pragma unroll
        for (int gk = 0; gk < C; gk++) r += s_acc[gk][tid];
        out[(size_t)b * C + tid] = r * (1.0f / Z);
    }
}

extern "C" void kernel_launch(void* const* d_in, const int* in_sizes, int n_in,
                              void* d_out, int out_size)
{
    const float* x      = (const float*)d_in[0];
    const float* keys   = (const float*)d_in[1];
    const float* values = (const float*)d_in[2];
    const float* gamma  = (const float*)d_in[3];
    float* out = (float*)d_out;

    const int B = in_sizes[0] / D;     // 2048
    nw_attn_kernel<<<B, NT>>>(x, keys, values, gamma, out);
}

// round 13
// speedup vs baseline: 1.2520x; 1.0213x over previous
#include <cuda_runtime.h>
#include <math_constants.h>

static constexpr int K  = 1024;
static constexpr int D  = 64;
static constexpr int C  = 32;
static constexpr int NT = 192;       // 6 warps
static constexpr int NW = NT / 32;
static constexpr int NG = NT / 8;    // 24 key-groups in pass 2

__global__ __launch_bounds__(NT, 7) void nw_attn_kernel(
    const float* __restrict__ x,
    const float* __restrict__ keys,
    const float* __restrict__ values,
    const float* __restrict__ gamma,
    float* __restrict__ out)
{
    __shared__ float s_scores[K];          // 4 KB scores
    __shared__ float s_red[NW];            // per-warp max
    __shared__ float s_z[NW];              // per-warp Z partials
    __shared__ float s_acc[NG][C + 1];     // padded rows: conflict-free columns

    const int b    = blockIdx.x;
    const int tid  = threadIdx.x;
    const int lane = tid & 31;
    const int warp = tid >> 5;

    const float g = gamma[0];

    // ---- Pass 1: 4 lanes per key, 8 keys per warp-iter (R3 pattern) ----
    const int l4 = lane & 3;               // dim-group of 16 floats
    const int kw = lane >> 2;              // key within 8-key tile

    const float* xb = x + (size_t)b * D + l4 * 16;
    const float4 xq0 = *reinterpret_cast<const float4*>(xb + 0);
    const float4 xq1 = *reinterpret_cast<const float4*>(xb + 4);
    const float4 xq2 = *reinterpret_cast<const float4*>(xb + 8);
    const float4 xq3 = *reinterpret_cast<const float4*>(xb + 12);

    const float* kb = keys + (size_t)b * K * D;

    float lmax = -CUDART_INF_F;
    #pragma unroll 2
    for (int k0 = warp * 8; k0 < K; k0 += NW * 8) {   // ~21 iters/warp
        const int key = k0 + kw;
        const float4* p = reinterpret_cast<const float4*>(
                              kb + (size_t)key * D + l4 * 16);
        // 4 independent 16B loads per lane (high MLP)
        const float4 a0 = __ldcs(p + 0);
        const float4 a1 = __ldcs(p + 1);
        const float4 a2 = __ldcs(p + 2);
        const float4 a3 = __ldcs(p + 3);

        float d, ss;
        d = xq0.x - a0.x; ss  = d * d;
        d = xq0.y - a0.y; ss = fmaf(d, d, ss);
        d = xq0.z - a0.z; ss = fmaf(d, d, ss);
        d = xq0.w - a0.w; ss = fmaf(d, d, ss);
        d = xq1.x - a1.x; ss = fmaf(d, d, ss);
        d = xq1.y - a1.y; ss = fmaf(d, d, ss);
        d = xq1.z - a1.z; ss = fmaf(d, d, ss);
        d = xq1.w - a1.w; ss = fmaf(d, d, ss);
        d = xq2.x - a2.x; ss = fmaf(d, d, ss);
        d = xq2.y - a2.y; ss = fmaf(d, d, ss);
        d = xq2.z - a2.z; ss = fmaf(d, d, ss);
        d = xq2.w - a2.w; ss = fmaf(d, d, ss);
        d = xq3.x - a3.x; ss = fmaf(d, d, ss);
        d = xq3.y - a3.y; ss = fmaf(d, d, ss);
        d = xq3.z - a3.z; ss = fmaf(d, d, ss);
        d = xq3.w - a3.w; ss = fmaf(d, d, ss);

        // reduce across the 4 lanes of this key
        ss += __shfl_xor_sync(0xffffffffu, ss, 1);
        ss += __shfl_xor_sync(0xffffffffu, ss, 2);

        const float s = -g * ss;
        if (l4 == 0) s_scores[key] = s;
        lmax = fmaxf(lmax, s);
    }

    // ---- block max ----
    #pragma unroll
    for (int o = 16; o; o >>= 1)
        lmax = fmaxf(lmax, __shfl_xor_sync(0xffffffffu, lmax, o));
    if (lane == 0) s_red[warp] = lmax;
    __syncthreads();                       // scores + maxes visible
    float M = s_red[0];
    #pragma unroll
    for (int w = 1; w < NW; w++) M = fmaxf(M, s_red[w]);

    // ---- Pass 2: exp on the fly + weighted sum over values ----
    const float* vb = values + (size_t)b * K * C;
    const int kgrp = tid >> 3;             // 0..23
    const int cq   = (tid & 7) * 4;        // channel offset
    const bool zlane = (tid & 7) == 0;

    float4 acc = make_float4(0.f, 0.f, 0.f, 0.f);
    float wsum = 0.f;
    #pragma unroll 4
    for (int i = 0; i < (K + NG - 1) / NG; i++) {   // 43 iters, last guarded
        const int k = kgrp + NG * i;
        if (k < K) {
            const float w = __expf(s_scores[k] - M);
            const float4 v = __ldcs(reinterpret_cast<const float4*>(
                                        vb + (size_t)k * C + cq));
            acc.x = fmaf(w, v.x, acc.x);
            acc.y = fmaf(w, v.y, acc.y);
            acc.z = fmaf(w, v.z, acc.z);
            acc.w = fmaf(w, v.w, acc.w);
            if (zlane) wsum += w;
        }
    }

    // Z: warp reduce (only zlane contributed), then per-warp partials
    #pragma unroll
    for (int o = 16; o; o >>= 1)
        wsum += __shfl_xor_sync(0xffffffffu, wsum, o);
    if (lane == 0) s_z[warp] = wsum;

    // scalar stores: 33-float row stride is not 16B-aligned, no STS.128
    s_acc[kgrp][cq + 0] = acc.x;
    s_acc[kgrp][cq + 1] = acc.y;
    s_acc[kgrp][cq + 2] = acc.z;
    s_acc[kgrp][cq + 3] = acc.w;
    __syncthreads();

    if (tid < C) {
        float Z = 0.f;
        #pragma unroll
        for (int w = 0; w < NW; w++) Z += s_z[w];
        float r = 0.f;
        #pragma unroll
        for (int gk = 0; gk < NG; gk++) r += s_acc[gk][tid];
        out[(size_t)b * C + tid] = r * (1.0f / Z);
    }
}

extern "C" void kernel_launch(void* const* d_in, const int* in_sizes, int n_in,
                              void* d_out, int out_size)
{
    const float* x      = (const float*)d_in[0];
    const float* keys   = (const float*)d_in[1];
    const float* values = (const float*)d_in[2];
    const float* gamma  = (const float*)d_in[3];
    float* out = (float*)d_out;

    const int B = in_sizes[0] / D;     // 2048
    nw_attn_kernel<<<B, NT>>>(x, keys, values, gamma, out);
}

// round 16
// speedup vs baseline: 1.3113x; 1.0474x over previous
#include <cuda_runtime.h>
#include <math_constants.h>

static constexpr int K    = 1024;
static constexpr int D    = 64;
static constexpr int C    = 32;
static constexpr int NT   = 256;
static constexpr int NW   = NT / 32;
static constexpr int GRID = 740;          // 148 SMs x 5 CTAs, single wave

__device__ __forceinline__ void pass1(
    const float* __restrict__ x, const float* __restrict__ keys,
    int b, float g, int warp, int lane,
    float* s_scores, float* s_red)
{
    const int l4 = lane & 3;
    const int kw = lane >> 2;

    const float* xb = x + (size_t)b * D + l4 * 16;
    const float4 xq0 = *reinterpret_cast<const float4*>(xb + 0);
    const float4 xq1 = *reinterpret_cast<const float4*>(xb + 4);
    const float4 xq2 = *reinterpret_cast<const float4*>(xb + 8);
    const float4 xq3 = *reinterpret_cast<const float4*>(xb + 12);

    const float* kb = keys + (size_t)b * K * D;

    float lmax = -CUDART_INF_F;
    #pragma unroll 2
    for (int k0 = warp * 8; k0 < K; k0 += NW * 8) {
        const int key = k0 + kw;
        const float4* p = reinterpret_cast<const float4*>(
                              kb + (size_t)key * D + l4 * 16);
        const float4 a0 = __ldcs(p + 0);
        const float4 a1 = __ldcs(p + 1);
        const float4 a2 = __ldcs(p + 2);
        const float4 a3 = __ldcs(p + 3);

        float d, ss;
        d = xq0.x - a0.x; ss  = d * d;
        d = xq0.y - a0.y; ss = fmaf(d, d, ss);
        d = xq0.z - a0.z; ss = fmaf(d, d, ss);
        d = xq0.w - a0.w; ss = fmaf(d, d, ss);
        d = xq1.x - a1.x; ss = fmaf(d, d, ss);
        d = xq1.y - a1.y; ss = fmaf(d, d, ss);
        d = xq1.z - a1.z; ss = fmaf(d, d, ss);
        d = xq1.w - a1.w; ss = fmaf(d, d, ss);
        d = xq2.x - a2.x; ss = fmaf(d, d, ss);
        d = xq2.y - a2.y; ss = fmaf(d, d, ss);
        d = xq2.z - a2.z; ss = fmaf(d, d, ss);
        d = xq2.w - a2.w; ss = fmaf(d, d, ss);
        d = xq3.x - a3.x; ss = fmaf(d, d, ss);
        d = xq3.y - a3.y; ss = fmaf(d, d, ss);
        d = xq3.z - a3.z; ss = fmaf(d, d, ss);
        d = xq3.w - a3.w; ss = fmaf(d, d, ss);

        ss += __shfl_xor_sync(0xffffffffu, ss, 1);
        ss += __shfl_xor_sync(0xffffffffu, ss, 2);

        const float s = -g * ss;
        if (l4 == 0) s_scores[key] = s;
        lmax = fmaxf(lmax, s);
    }
    #pragma unroll
    for (int o = 16; o; o >>= 1)
        lmax = fmaxf(lmax, __shfl_xor_sync(0xffffffffu, lmax, o));
    if (lane == 0) s_red[warp] = lmax;
}

__device__ __forceinline__ void pass2(
    const float* __restrict__ values, int b,
    const float* s_scores, float M,
    int tid, int lane, int warp,
    float* s_z, float (*s_acc)[C + 1])
{
    const float* vb = values + (size_t)b * K * C;
    const int kgrp = tid >> 3;
    const int cq   = (tid & 7) * 4;
    const bool zlane = (tid & 7) == 0;

    float4 acc = make_float4(0.f, 0.f, 0.f, 0.f);
    float wsum = 0.f;
    #pragma unroll 8
    for (int i = 0; i < K / 32; i++) {
        const int k = kgrp + 32 * i;
        const float w = __expf(s_scores[k] - M);
        const float4 v = __ldcs(reinterpret_cast<const float4*>(
                                    vb + (size_t)k * C + cq));
        acc.x = fmaf(w, v.x, acc.x);
        acc.y = fmaf(w, v.y, acc.y);
        acc.z = fmaf(w, v.z, acc.z);
        acc.w = fmaf(w, v.w, acc.w);
        if (zlane) wsum += w;
    }
    #pragma unroll
    for (int o = 16; o; o >>= 1)
        wsum += __shfl_xor_sync(0xffffffffu, wsum, o);
    if (lane == 0) s_z[warp] = wsum;

    s_acc[kgrp][cq + 0] = acc.x;
    s_acc[kgrp][cq + 1] = acc.y;
    s_acc[kgrp][cq + 2] = acc.z;
    s_acc[kgrp][cq + 3] = acc.w;
}

__device__ __forceinline__ void finalize(
    const float* s_z, const float (*s_acc)[C + 1], float* outp, int tid)
{
    if (tid < C) {
        float Z = 0.f;
        #pragma unroll
        for (int w = 0; w < NW; w++) Z += s_z[w];
        float r = 0.f;
        #pragma unroll
        for (int gk = 0; gk < C; gk++) r += s_acc[gk][tid];
        outp[tid] = r * (1.0f / Z);
    }
}

__global__ __launch_bounds__(NT, 5) void nw_attn_persist(
    const float* __restrict__ x,
    const float* __restrict__ keys,
    const float* __restrict__ values,
    const float* __restrict__ gamma,
    float* __restrict__ out,
    int B)
{
    __shared__ float s_scores[2][K];            // 8 KB
    __shared__ float s_red[2][NW];
    __shared__ float s_z[2][NW];
    __shared__ float s_acc[2][C][C + 1];        // 8.25 KB

    const int tid  = threadIdx.x;
    const int lane = tid & 31;
    const int warp = tid >> 5;
    const float g  = gamma[0];

    int p = 0;
    int prev_b = -1;

    for (int b = blockIdx.x; b < B; b += GRID) {
        pass1(x, keys, b, g, warp, lane, s_scores[p], s_red[p]);
        __syncthreads();   // scores[p]/red[p] visible; prev iter's z/acc[p^1] visible

        if (prev_b >= 0)
            finalize(s_z[p ^ 1], s_acc[p ^ 1], out + (size_t)prev_b * C, tid);

        float M = s_red[p][0];
        #pragma unroll
        for (int w = 1; w < NW; w++) M = fmaxf(M, s_red[p][w]);

        pass2(values, b, s_scores[p], M, tid, lane, warp, s_z[p], s_acc[p]);
        // no barrier: roll straight into next row's pass1 (other buffer)
        prev_b = b;
        p ^= 1;
    }

    __syncthreads();
    if (prev_b >= 0)
        finalize(s_z[p ^ 1], s_acc[p ^ 1], out + (size_t)prev_b * C, tid);
}

extern "C" void kernel_launch(void* const* d_in, const int* in_sizes, int n_in,
                              void* d_out, int out_size)
{
    const float* x      = (const float*)d_in[0];
    const float* keys   = (const float*)d_in[1];
    const float* values = (const float*)d_in[2];
    const float* gamma  = (const float*)d_in[3];
    float* out = (float*)d_out;

    const int B = in_sizes[0] / D;     // 2048
    nw_attn_persist<<<GRID, NT>>>(x, keys, values, gamma, out, B);
}

// round 17
// speedup vs baseline: 1.3116x; 1.0003x over previous
#include <cuda_runtime.h>
#include <math_constants.h>

static constexpr int K    = 1024;
static constexpr int D    = 64;
static constexpr int C    = 32;
static constexpr int NT   = 256;
static constexpr int NW   = NT / 32;
static constexpr int GRID = 683;          // ceil(2048/3): every CTA exactly 3 rows
                                          // (one CTA 2) -> zero tail imbalance

__device__ __forceinline__ void pass1(
    const float* __restrict__ x, const float* __restrict__ keys,
    int b, float g, int warp, int lane,
    float* s_scores, float* s_red)
{
    const int l4 = lane & 3;
    const int kw = lane >> 2;

    const float* xb = x + (size_t)b * D + l4 * 16;
    const float4 xq0 = *reinterpret_cast<const float4*>(xb + 0);
    const float4 xq1 = *reinterpret_cast<const float4*>(xb + 4);
    const float4 xq2 = *reinterpret_cast<const float4*>(xb + 8);
    const float4 xq3 = *reinterpret_cast<const float4*>(xb + 12);

    const float* kb = keys + (size_t)b * K * D;

    float lmax = -CUDART_INF_F;
    #pragma unroll 2
    for (int k0 = warp * 8; k0 < K; k0 += NW * 8) {
        const int key = k0 + kw;
        const float4* p = reinterpret_cast<const float4*>(
                              kb + (size_t)key * D + l4 * 16);
        const float4 a0 = __ldcs(p + 0);
        const float4 a1 = __ldcs(p + 1);
        const float4 a2 = __ldcs(p + 2);
        const float4 a3 = __ldcs(p + 3);

        float d, ss;
        d = xq0.x - a0.x; ss  = d * d;
        d = xq0.y - a0.y; ss = fmaf(d, d, ss);
        d = xq0.z - a0.z; ss = fmaf(d, d, ss);
        d = xq0.w - a0.w; ss = fmaf(d, d, ss);
        d = xq1.x - a1.x; ss = fmaf(d, d, ss);
        d = xq1.y - a1.y; ss = fmaf(d, d, ss);
        d = xq1.z - a1.z; ss = fmaf(d, d, ss);
        d = xq1.w - a1.w; ss = fmaf(d, d, ss);
        d = xq2.x - a2.x; ss = fmaf(d, d, ss);
        d = xq2.y - a2.y; ss = fmaf(d, d, ss);
        d = xq2.z - a2.z; ss = fmaf(d, d, ss);
        d = xq2.w - a2.w; ss = fmaf(d, d, ss);
        d = xq3.x - a3.x; ss = fmaf(d, d, ss);
        d = xq3.y - a3.y; ss = fmaf(d, d, ss);
        d = xq3.z - a3.z; ss = fmaf(d, d, ss);
        d = xq3.w - a3.w; ss = fmaf(d, d, ss);

        ss += __shfl_xor_sync(0xffffffffu, ss, 1);
        ss += __shfl_xor_sync(0xffffffffu, ss, 2);

        const float s = -g * ss;
        if (l4 == 0) s_scores[key] = s;
        lmax = fmaxf(lmax, s);
    }
    #pragma unroll
    for (int o = 16; o; o >>= 1)
        lmax = fmaxf(lmax, __shfl_xor_sync(0xffffffffu, lmax, o));
    if (lane == 0) s_red[warp] = lmax;
}

__device__ __forceinline__ void pass2(
    const float* __restrict__ values, int b,
    const float* s_scores, float M,
    int tid, int lane, int warp,
    float* s_z, float (*s_acc)[C + 1])
{
    const float* vb = values + (size_t)b * K * C;
    const int kgrp = tid >> 3;
    const int cq   = (tid & 7) * 4;
    const bool zlane = (tid & 7) == 0;

    float4 acc = make_float4(0.f, 0.f, 0.f, 0.f);
    float wsum = 0.f;
    #pragma unroll 8
    for (int i = 0; i < K / 32; i++) {
        const int k = kgrp + 32 * i;
        const float w = __expf(s_scores[k] - M);
        const float4 v = __ldcs(reinterpret_cast<const float4*>(
                                    vb + (size_t)k * C + cq));
        acc.x = fmaf(w, v.x, acc.x);
        acc.y = fmaf(w, v.y, acc.y);
        acc.z = fmaf(w, v.z, acc.z);
        acc.w = fmaf(w, v.w, acc.w);
        if (zlane) wsum += w;
    }
    #pragma unroll
    for (int o = 16; o; o >>= 1)
        wsum += __shfl_xor_sync(0xffffffffu, wsum, o);
    if (lane == 0) s_z[warp] = wsum;

    s_acc[kgrp][cq + 0] = acc.x;
    s_acc[kgrp][cq + 1] = acc.y;
    s_acc[kgrp][cq + 2] = acc.z;
    s_acc[kgrp][cq + 3] = acc.w;
}

__device__ __forceinline__ void finalize(
    const float* s_z, const float (*s_acc)[C + 1], float* outp, int tid)
{
    if (tid < C) {
        float Z = 0.f;
        #pragma unroll
        for (int w = 0; w < NW; w++) Z += s_z[w];
        float r = 0.f;
        #pragma unroll
        for (int gk = 0; gk < C; gk++) r += s_acc[gk][tid];
        outp[tid] = r * (1.0f / Z);
    }
}

__global__ __launch_bounds__(NT, 5) void nw_attn_persist(
    const float* __restrict__ x,
    const float* __restrict__ keys,
    const float* __restrict__ values,
    const float* __restrict__ gamma,
    float* __restrict__ out,
    int B)
{
    __shared__ float s_scores[2][K];            // 8 KB
    __shared__ float s_red[2][NW];
    __shared__ float s_z[2][NW];
    __shared__ float s_acc[2][C][C + 1];        // 8.25 KB

    const int tid  = threadIdx.x;
    const int lane = tid & 31;
    const int warp = tid >> 5;
    const float g  = gamma[0];

    int p = 0;
    int prev_b = -1;

    for (int b = blockIdx.x; b < B; b += GRID) {
        pass1(x, keys, b, g, warp, lane, s_scores[p], s_red[p]);
        __syncthreads();   // scores[p]/red[p] visible; prev iter's z/acc[p^1] visible

        if (prev_b >= 0)
            finalize(s_z[p ^ 1], s_acc[p ^ 1], out + (size_t)prev_b * C, tid);

        float M = s_red[p][0];
        #pragma unroll
        for (int w = 1; w < NW; w++) M = fmaxf(M, s_red[p][w]);

        pass2(values, b, s_scores[p], M, tid, lane, warp, s_z[p], s_acc[p]);
        // no barrier: roll straight into next row's pass1 (other buffer)
        prev_b = b;
        p ^= 1;
    }

    __syncthreads();
    if (prev_b >= 0)
        finalize(s_z[p ^ 1], s_acc[p ^ 1], out + (size_t)prev_b * C, tid);
}

extern "C" void kernel_launch(void* const* d_in, const int* in_sizes, int n_in,
                              void* d_out, int out_size)
{
    const float* x      = (const float*)d_in[0];
    const float* keys   = (const float*)d_in[1];
    const float* values = (const float*)d_in[2];
    const float* gamma  = (const float*)d_in[3];
    float* out = (float*)d_out;

    const int B = in_sizes[0] / D;     // 2048
    nw_attn_persist<<<GRID, NT>>>(x, keys, values, gamma, out, B);
}